// round 3
// baseline (speedup 1.0000x reference)
#include <cuda_runtime.h>

// SSIM loss, fully fused single pass + tiny finalize.
// Layout: 32*3 = 96 planes of 512x512 fp32.
// Separable 3x3 Gaussian (sigma=1.5), zero padding, taps as immediates.

#define HW 512
#define PLANE (HW * HW)
#define NPLANES 96
#define ROWS_PB 32              // output rows per block
#define TPB 128                 // threads per block; each thread does 4 cols -> 512 wide
#define GRID_X (HW / ROWS_PB)   // 16
#define NBLOCKS (GRID_X * NPLANES)  // 1536

// fp32 Gaussian taps: g = exp(-[1,0,1]/4.5), normalized
__device__ __constant__ float kDummy; // (unused; keeps nvcc happy about empty cu sections)
#define W0 0.3078013f
#define W1 0.3843974f
#define C1f 1.0e-4f
#define C2f 9.0e-4f

__device__ float g_partials[NBLOCKS];

__global__ __launch_bounds__(TPB) void ssim_main(const float* __restrict__ img1,
                                                 const float* __restrict__ img2) {
    const int plane = blockIdx.y;
    const int y0 = blockIdx.x * ROWS_PB;
    const int x0 = threadIdx.x * 4;

    const float* p1 = img1 + (size_t)plane * PLANE;
    const float* p2 = img2 + (size_t)plane * PLANE;

    // vertical streaming partial sums for 5 quantities x 4 cols
    float acc0[5][4];
    float acc1[5][4];
#pragma unroll
    for (int q = 0; q < 5; ++q)
#pragma unroll
        for (int i = 0; i < 4; ++i) { acc0[q][i] = 0.f; acc1[q][i] = 0.f; }

    float tsum = 0.f;

    for (int j = 0; j <= ROWS_PB + 1; ++j) {
        const int y = y0 - 1 + j;
        float a[6], b[6];
        if (y >= 0 && y < HW) {
            const float* r1 = p1 + y * HW;
            const float* r2 = p2 + y * HW;
            float4 A = *reinterpret_cast<const float4*>(r1 + x0);
            float4 B = *reinterpret_cast<const float4*>(r2 + x0);
            a[1] = A.x; a[2] = A.y; a[3] = A.z; a[4] = A.w;
            b[1] = B.x; b[2] = B.y; b[3] = B.z; b[4] = B.w;
            a[0] = (x0 > 0) ? r1[x0 - 1] : 0.f;
            b[0] = (x0 > 0) ? r2[x0 - 1] : 0.f;
            a[5] = (x0 + 4 < HW) ? r1[x0 + 4] : 0.f;
            b[5] = (x0 + 4 < HW) ? r2[x0 + 4] : 0.f;
        } else {
#pragma unroll
            for (int k = 0; k < 6; ++k) { a[k] = 0.f; b[k] = 0.f; }
        }

        // per-pixel products (shared across horizontal taps)
        float aa[6], bb[6], ab[6];
#pragma unroll
        for (int k = 0; k < 6; ++k) {
            aa[k] = a[k] * a[k];
            bb[k] = b[k] * b[k];
            ab[k] = a[k] * b[k];
        }

        // horizontal filter: h[q][i], center at index i+1
        float h[5][4];
#pragma unroll
        for (int i = 0; i < 4; ++i) {
            h[0][i] = fmaf(W1, a[i + 1],  W0 * (a[i]  + a[i + 2]));
            h[1][i] = fmaf(W1, b[i + 1],  W0 * (b[i]  + b[i + 2]));
            h[2][i] = fmaf(W1, aa[i + 1], W0 * (aa[i] + aa[i + 2]));
            h[3][i] = fmaf(W1, bb[i + 1], W0 * (bb[i] + bb[i + 2]));
            h[4][i] = fmaf(W1, ab[i + 1], W0 * (ab[i] + ab[i + 2]));
        }

        // emit output row (y - 1) once we've seen its bottom neighbor
        if (j >= 2) {
#pragma unroll
            for (int i = 0; i < 4; ++i) {
                const float mu1 = fmaf(W0, h[0][i], acc0[0][i]);
                const float mu2 = fmaf(W0, h[1][i], acc0[1][i]);
                const float e11 = fmaf(W0, h[2][i], acc0[2][i]);
                const float e22 = fmaf(W0, h[3][i], acc0[3][i]);
                const float e12 = fmaf(W0, h[4][i], acc0[4][i]);

                const float mu1s = mu1 * mu1;
                const float mu2s = mu2 * mu2;
                const float mu12 = mu1 * mu2;
                const float s1 = e11 - mu1s;
                const float s2 = e22 - mu2s;
                const float s12 = e12 - mu12;
                const float num = fmaf(2.f, mu12, C1f) * fmaf(2.f, s12, C2f);
                const float den = (mu1s + mu2s + C1f) * (s1 + s2 + C2f);
                tsum += __fdividef(num, den);
            }
        }

        // advance vertical partials
#pragma unroll
        for (int q = 0; q < 5; ++q)
#pragma unroll
            for (int i = 0; i < 4; ++i) {
                acc0[q][i] = fmaf(W1, h[q][i], acc1[q][i]);
                acc1[q][i] = W0 * h[q][i];
            }
    }

    // block reduction (deterministic): warp shuffle -> smem -> single partial
#pragma unroll
    for (int off = 16; off; off >>= 1)
        tsum += __shfl_down_sync(0xffffffffu, tsum, off);

    __shared__ float warp_sums[TPB / 32];
    const int lane = threadIdx.x & 31;
    const int wid = threadIdx.x >> 5;
    if (lane == 0) warp_sums[wid] = tsum;
    __syncthreads();
    if (threadIdx.x == 0) {
        float s = 0.f;
#pragma unroll
        for (int w = 0; w < TPB / 32; ++w) s += warp_sums[w];
        g_partials[blockIdx.y * GRID_X + blockIdx.x] = s;
    }
}

__global__ __launch_bounds__(256) void ssim_finalize(float* __restrict__ out) {
    __shared__ double sh[256];
    double s = 0.0;
    for (int i = threadIdx.x; i < NBLOCKS; i += 256) s += (double)g_partials[i];
    sh[threadIdx.x] = s;
    __syncthreads();
    for (int off = 128; off; off >>= 1) {
        if (threadIdx.x < off) sh[threadIdx.x] += sh[threadIdx.x + off];
        __syncthreads();
    }
    if (threadIdx.x == 0) out[0] = (float)(1.0 - sh[0]);
}

extern "C" void kernel_launch(void* const* d_in, const int* in_sizes, int n_in,
                              void* d_out, int out_size) {
    const float* img1 = (const float*)d_in[0];
    const float* img2 = (const float*)d_in[1];
    float* out = (float*)d_out;
    (void)in_sizes; (void)n_in; (void)out_size;

    dim3 grid(GRID_X, NPLANES);
    ssim_main<<<grid, TPB>>>(img1, img2);
    ssim_finalize<<<1, 256>>>(out);
}